// round 2
// baseline (speedup 1.0000x reference)
#include <cuda_runtime.h>

// Problem constants
#define BATCH 8
#define CINCH 128
#define GRPS  8
#define HDIM  128
#define WDIM  128
// per-branch pooled grid sizes (oh, ow): (1,11),(11,1),(3,5),(5,3)

// ---- device scratch (no allocations allowed) ----
__device__ float g_pool[4 * 8 * 128 * 15];   // [br][b][c][pos]
__device__ float g_q[4 * 8 * 128 * 15];      // after branch linear
__device__ float g_Wfold[8 * 96 * 16];       // Whh @ W_center per group
__device__ float g_Gi[8 * 8 * 96 * 15];      // [b][g][o][pos] GRU-input grid (incl. bih)

__device__ __forceinline__ float sigf(float x) {
    return __fdividef(1.0f, 1.0f + __expf(-x));
}
__device__ __forceinline__ float tanh_fast(float x) {
    x = fminf(fmaxf(x, -15.0f), 15.0f);
    float e = __expf(2.0f * x);
    return __fdividef(e - 1.0f, e + 1.0f);
}

// ============================================================================
// K1: adaptive avg pools. 52 rectangle means per (b,c). Block per (b,c).
// ============================================================================
__global__ void pool_kernel(const float* __restrict__ x) {
    int bc = blockIdx.x;            // 0..1023
    int b = bc >> 7, c = bc & 127;
    const float* tile = x + (size_t)bc * (HDIM * WDIM);
    int lane = threadIdx.x & 31, warp = threadIdx.x >> 5;

    for (int oi = warp; oi < 52; oi += 8) {
        int br, pos, hs, he, ws, we;
        if (oi < 11) {
            br = 0; pos = oi;
            hs = 0; he = 128;
            ws = (pos * 128) / 11; we = ((pos + 1) * 128 + 10) / 11;
        } else if (oi < 22) {
            br = 1; pos = oi - 11;
            ws = 0; we = 128;
            hs = (pos * 128) / 11; he = ((pos + 1) * 128 + 10) / 11;
        } else if (oi < 37) {
            br = 2; pos = oi - 22;
            int i = pos / 5, jj = pos % 5;
            hs = (i * 128) / 3;  he = ((i + 1) * 128 + 2) / 3;
            ws = (jj * 128) / 5; we = ((jj + 1) * 128 + 4) / 5;
        } else {
            br = 3; pos = oi - 37;
            int i = pos / 3, jj = pos % 3;
            hs = (i * 128) / 5;  he = ((i + 1) * 128 + 4) / 5;
            ws = (jj * 128) / 3; we = ((jj + 1) * 128 + 2) / 3;
        }
        float s = 0.0f;
        for (int h = hs; h < he; h++) {
            const float* row = tile + h * WDIM;
            for (int w = ws + lane; w < we; w += 32) s += row[w];
        }
        #pragma unroll
        for (int off = 16; off; off >>= 1) s += __shfl_down_sync(0xffffffffu, s, off);
        if (lane == 0)
            g_pool[((br * 8 + b) * 128 + c) * 15 + pos] =
                s / (float)((he - hs) * (we - ws));
    }
}

// ============================================================================
// K2: per-branch linear on flattened pooled grid: q = W @ p + b
// Block per (br, b); thread = channel.
// ============================================================================
__global__ void lin_kernel(const float* __restrict__ W0, const float* __restrict__ b0,
                           const float* __restrict__ W1, const float* __restrict__ b1,
                           const float* __restrict__ W2, const float* __restrict__ b2,
                           const float* __restrict__ W3, const float* __restrict__ b3) {
    int blk = blockIdx.x;           // 0..31
    int br = blk >> 3, b = blk & 7;
    int c = threadIdx.x;            // 0..127
    const float* Ws[4] = {W0, W1, W2, W3};
    const float* bs[4] = {b0, b1, b2, b3};
    int cd = (br < 2) ? 11 : 15;
    const float* W = Ws[br];
    const float* bb = bs[br];
    float p[15];
    const float* src = g_pool + ((br * 8 + b) * 128 + c) * 15;
    for (int d = 0; d < cd; d++) p[d] = src[d];
    float* dst = g_q + ((br * 8 + b) * 128 + c) * 15;
    for (int m = 0; m < cd; m++) {
        float s = bb[m];
        for (int d = 0; d < cd; d++) s = fmaf(W[m * cd + d], p[d], s);
        dst[m] = s;
    }
}

// ============================================================================
// K3a: Wfold[g] = Whh[g] @ W_center[g]   (96x32 @ 32x16 -> 96x16)
// ============================================================================
__global__ void fold_kernel(const float* __restrict__ Whh, const float* __restrict__ Wcen) {
    int g = blockIdx.x;             // 0..7
    int o = threadIdx.x;            // 0..95
    for (int i = 0; i < 16; i++) {
        float s = 0.0f;
        for (int hh = 0; hh < 32; hh++)
            s = fmaf(Whh[(g * 96 + o) * 32 + hh], Wcen[(g * 32 + hh) * 16 + i], s);
        g_Wfold[(g * 96 + o) * 16 + i] = s;
    }
}

// ============================================================================
// K3b: Gi_grid[b,g,o,pos] = bih[g,o] + sum_f Wih[g,o,f] * B_grid[b,g,f,pos]
// where B_grid folds the grouped merge conv into the branch grid q.
// Block per (b,g).
// ============================================================================
__global__ void gi_kernel(const float* __restrict__ Wm, const float* __restrict__ Wih,
                          const float* __restrict__ bih) {
    int bg = blockIdx.x;            // 0..63
    int b = bg >> 3, g = bg & 7;
    int br = g >> 1;
    int GS = (br < 2) ? 11 : 15;
    __shared__ float Bs[32 * 15];
    int t = threadIdx.x;            // 128 threads

    for (int idx = t; idx < 32 * GS; idx += 128) {
        int f = idx / GS, pos = idx - f * GS;
        int i = 16 * g + (f >> 1);
        int jm = f & 1;
        int lcb = 64 * (g & 1) + 4 * (f >> 1);
        const float* qb = g_q + ((br * 8 + b) * 128 + lcb) * 15 + pos;
        float s = 0.0f;
        #pragma unroll
        for (int k = 0; k < 4; k++)
            s = fmaf(Wm[(i * 2 + jm) * 4 + k], qb[k * 15], s);
        Bs[f * GS + pos] = s;
    }
    __syncthreads();
    for (int idx = t; idx < 96 * GS; idx += 128) {
        int o = idx / GS, pos = idx - o * GS;
        float s = bih[g * 96 + o];
        for (int f = 0; f < 32; f++)
            s = fmaf(Wih[(g * 96 + o) * 32 + f], Bs[f * GS + pos], s);
        g_Gi[((b * 8 + g) * 96 + o) * 15 + pos] = s;
    }
}

// ============================================================================
// K4: main fused kernel.
// grid = (128, 8): blockIdx.y = GRU group, blockIdx.x = 8-row tile.
// Warp <-> one image row; thread owns 4 consecutive w pixels (float4 I/O).
// Per pixel: cg + gh via Wfold (128x16 grouped matmul from registers),
// gi via 4-corner bilinear gather from smem Gi grid, then GRUCell elementwise.
// ============================================================================
__global__ __launch_bounds__(256) void main_kernel(const float* __restrict__ x,
                                                   const float* __restrict__ Wcen,
                                                   const float* __restrict__ bhh,
                                                   float* __restrict__ out) {
    const int g = blockIdx.y;
    const int br = g >> 1;
    const int oh = (br == 0) ? 1 : (br == 1) ? 11 : (br == 2) ? 3 : 5;
    const int ow = (br == 0) ? 11 : (br == 1) ? 1 : (br == 2) ? 5 : 3;
    const int GS = oh * ow;

    __shared__ float Wf_s[96 * 16];
    __shared__ float Wc_s[32 * 16];
    __shared__ float bhh_s[96];
    __shared__ float Gi_s[96 * 15];

    const int t = threadIdx.x;
    const int b = blockIdx.x >> 4;  // 16 blocks per batch (128 rows / 8 rows-per-block)

    for (int idx = t; idx < 96 * 16; idx += 256) Wf_s[idx] = g_Wfold[g * 96 * 16 + idx];
    for (int idx = t; idx < 32 * 16; idx += 256) Wc_s[idx] = Wcen[g * 32 * 16 + idx];
    if (t < 96) bhh_s[t] = bhh[g * 96 + t];
    for (int idx = t; idx < 96 * GS; idx += 256) {
        int o = idx / GS, pos = idx - o * GS;
        Gi_s[idx] = g_Gi[((b * 8 + g) * 96 + o) * 15 + pos];
    }
    __syncthreads();

    const int warp = t >> 5, lane = t & 31;
    const int r = blockIdx.x * 8 + warp;   // global row 0..1023
    const int h = r & 127;
    const int wbase = lane * 4;

    // bilinear params (align_corners=True); oh==1 / ow==1 -> repeat
    int ih0, ih1; float fh;
    if (oh == 1) { ih0 = ih1 = 0; fh = 0.0f; }
    else {
        float src = (float)(h * (oh - 1)) * (1.0f / 127.0f);
        ih0 = (int)src; if (ih0 > oh - 2) ih0 = oh - 2;
        fh = src - (float)ih0; ih1 = ih0 + 1;
    }
    int p00[4], p01[4], p10[4], p11[4];
    float w00[4], w01[4], w10[4], w11[4];
    #pragma unroll
    for (int s = 0; s < 4; s++) {
        int w = wbase + s;
        int j0, j1; float fw;
        if (ow == 1) { j0 = j1 = 0; fw = 0.0f; }
        else {
            float src = (float)(w * (ow - 1)) * (1.0f / 127.0f);
            j0 = (int)src; if (j0 > ow - 2) j0 = ow - 2;
            fw = src - (float)j0; j1 = j0 + 1;
        }
        p00[s] = ih0 * ow + j0; p01[s] = ih0 * ow + j1;
        p10[s] = ih1 * ow + j0; p11[s] = ih1 * ow + j1;
        w00[s] = (1.0f - fh) * (1.0f - fw); w01[s] = (1.0f - fh) * fw;
        w10[s] = fh * (1.0f - fw);          w11[s] = fh * fw;
    }

    // load this group's 16 input channels for the 4 pixels (coalesced float4)
    float xq[16][4];
    const float* xb = x + (((size_t)b * CINCH + g * 16) * HDIM + h) * WDIM + wbase;
    #pragma unroll
    for (int c = 0; c < 16; c++) {
        float4 v = *(const float4*)(xb + (size_t)c * (HDIM * WDIM));
        xq[c][0] = v.x; xq[c][1] = v.y; xq[c][2] = v.z; xq[c][3] = v.w;
    }

    float* outb = out + (((size_t)b * 256) * HDIM + h) * WDIM + wbase;

    for (int j = 0; j < 32; j++) {
        float hr[4], hz[4], hn[4], cgv[4];
        float bj0 = bhh_s[j], bj1 = bhh_s[32 + j], bj2 = bhh_s[64 + j];
        #pragma unroll
        for (int s = 0; s < 4; s++) { hr[s] = bj0; hz[s] = bj1; hn[s] = bj2; cgv[s] = 0.0f; }

        const float* wr = Wf_s + j * 16;
        const float* wz = Wf_s + (32 + j) * 16;
        const float* wn = Wf_s + (64 + j) * 16;
        const float* wc = Wc_s + j * 16;
        #pragma unroll
        for (int i = 0; i < 16; i++) {
            float ar = wr[i], az = wz[i], an = wn[i], ac = wc[i];
            #pragma unroll
            for (int s = 0; s < 4; s++) {
                float xv = xq[i][s];
                hr[s]  = fmaf(ar, xv, hr[s]);
                hz[s]  = fmaf(az, xv, hz[s]);
                hn[s]  = fmaf(an, xv, hn[s]);
                cgv[s] = fmaf(ac, xv, cgv[s]);
            }
        }

        const float* Qr = Gi_s + j * GS;
        const float* Qz = Gi_s + (32 + j) * GS;
        const float* Qn = Gi_s + (64 + j) * GS;
        float res[4];
        #pragma unroll
        for (int s = 0; s < 4; s++) {
            float gir = w00[s] * Qr[p00[s]] + w01[s] * Qr[p01[s]]
                      + w10[s] * Qr[p10[s]] + w11[s] * Qr[p11[s]];
            float giz = w00[s] * Qz[p00[s]] + w01[s] * Qz[p01[s]]
                      + w10[s] * Qz[p10[s]] + w11[s] * Qz[p11[s]];
            float gin = w00[s] * Qn[p00[s]] + w01[s] * Qn[p01[s]]
                      + w10[s] * Qn[p10[s]] + w11[s] * Qn[p11[s]];
            float rr = sigf(gir + hr[s]);
            float zz = sigf(giz + hz[s]);
            float nn = tanh_fast(gin + rr * hn[s]);
            res[s] = nn + zz * (cgv[s] - nn);   // (1-z)*n + z*cg
        }
        *(float4*)(outb + (size_t)(j * 8 + g) * (HDIM * WDIM)) =
            make_float4(res[0], res[1], res[2], res[3]);
    }
}

// ============================================================================
extern "C" void kernel_launch(void* const* d_in, const int* in_sizes, int n_in,
                              void* d_out, int out_size) {
    (void)in_sizes; (void)n_in; (void)out_size;
    const float* x    = (const float*)d_in[0];
    const float* Wcen = (const float*)d_in[1];
    const float* W0 = (const float*)d_in[2];  const float* b0 = (const float*)d_in[3];
    const float* W1 = (const float*)d_in[4];  const float* b1 = (const float*)d_in[5];
    const float* W2 = (const float*)d_in[6];  const float* b2 = (const float*)d_in[7];
    const float* W3 = (const float*)d_in[8];  const float* b3 = (const float*)d_in[9];
    const float* Wm  = (const float*)d_in[10];
    const float* Wih = (const float*)d_in[11];
    const float* Whh = (const float*)d_in[12];
    const float* bih = (const float*)d_in[13];
    const float* bhh = (const float*)d_in[14];
    float* out = (float*)d_out;

    pool_kernel<<<1024, 256>>>(x);
    lin_kernel<<<32, 128>>>(W0, b0, W1, b1, W2, b2, W3, b3);
    fold_kernel<<<8, 96>>>(Whh, Wcen);
    gi_kernel<<<64, 128>>>(Wm, Wih, bih);
    main_kernel<<<dim3(128, 8), 256>>>(x, Wcen, bhh, out);
}

// round 3
// speedup vs baseline: 2.3004x; 2.3004x over previous
#include <cuda_runtime.h>
#include <stdint.h>

#define BATCH 8
#define CINCH 128
#define GRPS  8
#define HDIM  128
#define WDIM  128

// ---- device scratch ----
__device__ float g_pool[4 * 8 * 128 * 15];   // [br][b][c][pos]
__device__ float g_Wfold[8 * 96 * 16];       // Whh @ W_center per group
__device__ float g_Gi[8 * 8 * 96 * 15];      // [b][g][o][pos]

// ---- helpers ----
__device__ __forceinline__ float tanhfast(float x) {
    float y; asm("tanh.approx.f32 %0, %1;" : "=f"(y) : "f"(x)); return y;
}
__device__ __forceinline__ float sigfast(float x) {
    return fmaf(0.5f, tanhfast(0.5f * x), 0.5f);
}
__device__ __forceinline__ uint64_t pack2(float a, float b) {
    uint64_t r; asm("mov.b64 %0, {%1,%2};" : "=l"(r) : "f"(a), "f"(b)); return r;
}
__device__ __forceinline__ void unpack2(uint64_t v, float& a, float& b) {
    asm("mov.b64 {%0,%1}, %2;" : "=f"(a), "=f"(b) : "l"(v));
}
__device__ __forceinline__ void ffma2(uint64_t& d, uint64_t a, uint64_t b) {
    asm("fma.rn.f32x2 %0, %1, %2, %0;" : "+l"(d) : "l"(a), "l"(b));
}

// ============================================================================
// K1: single-pass adaptive pools. Block per (b,c), 128 threads = columns.
// Each thread scans its column once; h-bin membership is compile-time via
// full unroll. Overlapping bins: row h also in bin p+1 iff
// h == floor((p+1)*128/o) and (p+1)*128 % o != 0.
// ============================================================================
__global__ __launch_bounds__(128) void pool_kernel(const float* __restrict__ x) {
    const int bc = blockIdx.x;            // 0..1023
    const int b = bc >> 7, c = bc & 127;
    const float* tile = x + (size_t)bc * (HDIM * WDIM);
    const int t = threadIdx.x;            // column w

    float a0 = 0.0f;
    float a1[11], a2[3], a3[5];
    #pragma unroll
    for (int i = 0; i < 11; i++) a1[i] = 0.0f;
    #pragma unroll
    for (int i = 0; i < 3; i++) a2[i] = 0.0f;
    #pragma unroll
    for (int i = 0; i < 5; i++) a3[i] = 0.0f;

    #pragma unroll
    for (int h = 0; h < 128; h++) {
        float v = tile[h * 128 + t];
        a0 += v;
        {   // o = 11
            const int p = (h * 11) >> 7;
            a1[p] += v;
            if (p + 1 < 11 && h == ((p + 1) * 128) / 11 && (((p + 1) * 128) % 11) != 0)
                a1[p + 1] += v;
        }
        {   // o = 3
            const int p = (h * 3) >> 7;
            a2[p] += v;
            if (p + 1 < 3 && h == ((p + 1) * 128) / 3 && (((p + 1) * 128) % 3) != 0)
                a2[p + 1] += v;
        }
        {   // o = 5
            const int p = (h * 5) >> 7;
            a3[p] += v;
            if (p + 1 < 5 && h == ((p + 1) * 128) / 5 && (((p + 1) * 128) % 5) != 0)
                a3[p + 1] += v;
        }
    }

    __shared__ float cs[20][128];
    cs[0][t] = a0;
    #pragma unroll
    for (int i = 0; i < 11; i++) cs[1 + i][t] = a1[i];
    #pragma unroll
    for (int i = 0; i < 3; i++) cs[12 + i][t] = a2[i];
    #pragma unroll
    for (int i = 0; i < 5; i++) cs[15 + i][t] = a3[i];
    __syncthreads();

    const int warp = t >> 5, lane = t & 31;
    for (int oi = warp; oi < 52; oi += 4) {
        int br, pos, row, ws, we, hs, he;
        if (oi < 11) {
            br = 0; pos = oi; row = 0;
            hs = 0; he = 128;
            ws = (pos * 128) / 11; we = ((pos + 1) * 128 + 10) / 11;
        } else if (oi < 22) {
            br = 1; pos = oi - 11; row = 1 + pos;
            ws = 0; we = 128;
            hs = (pos * 128) / 11; he = ((pos + 1) * 128 + 10) / 11;
        } else if (oi < 37) {
            br = 2; pos = oi - 22;
            int i = pos / 5, jj = pos % 5;
            row = 12 + i;
            hs = (i * 128) / 3;  he = ((i + 1) * 128 + 2) / 3;
            ws = (jj * 128) / 5; we = ((jj + 1) * 128 + 4) / 5;
        } else {
            br = 3; pos = oi - 37;
            int i = pos / 3, jj = pos % 3;
            row = 15 + i;
            hs = (i * 128) / 5;  he = ((i + 1) * 128 + 4) / 5;
            ws = (jj * 128) / 3; we = ((jj + 1) * 128 + 2) / 3;
        }
        float s = 0.0f;
        for (int w = ws + lane; w < we; w += 32) s += cs[row][w];
        #pragma unroll
        for (int off = 16; off; off >>= 1) s += __shfl_down_sync(0xffffffffu, s, off);
        if (lane == 0)
            g_pool[((br * 8 + b) * 128 + c) * 15 + pos] =
                s / (float)((he - hs) * (we - ws));
    }
}

// ============================================================================
// K2: Wfold[g] = Whh[g] @ W_center[g]   (96x32 @ 32x16 -> 96x16)
// ============================================================================
__global__ void fold_kernel(const float* __restrict__ Whh, const float* __restrict__ Wcen) {
    int g = blockIdx.x;             // 0..7
    int o = threadIdx.x;            // 0..95
    #pragma unroll 4
    for (int i = 0; i < 16; i++) {
        float s = 0.0f;
        #pragma unroll
        for (int hh = 0; hh < 32; hh++)
            s = fmaf(Whh[(g * 96 + o) * 32 + hh], Wcen[(g * 32 + hh) * 16 + i], s);
        g_Wfold[(g * 96 + o) * 16 + i] = s;
    }
}

// ============================================================================
// K3: fused branch-linear + merge + Wih  -> Gi grid. Block per (b,g), 256 thr.
// ============================================================================
__global__ __launch_bounds__(256) void gi_kernel(
    const float* __restrict__ W0, const float* __restrict__ b0,
    const float* __restrict__ W1, const float* __restrict__ b1,
    const float* __restrict__ W2, const float* __restrict__ b2,
    const float* __restrict__ W3, const float* __restrict__ b3,
    const float* __restrict__ Wm, const float* __restrict__ Wih,
    const float* __restrict__ bih)
{
    const int blk = blockIdx.x;     // 0..63
    const int b = blk >> 3, g = blk & 7;
    const int br = g >> 1;
    const int GS = (br < 2) ? 11 : 15;
    const float* Ws[4] = {W0, W1, W2, W3};
    const float* bs[4] = {b0, b1, b2, b3};
    const float* W = Ws[br];
    const float* bias = bs[br];
    const int t = threadIdx.x;
    const int c0 = 64 * (g & 1);

    __shared__ float q[64 * 15];
    __shared__ float Bs[32 * 15];

    // branch linear for the 64 channels this group consumes
    for (int idx = t; idx < 64 * GS; idx += 256) {
        int cc = idx / GS, m = idx - cc * GS;
        const float* src = g_pool + ((br * 8 + b) * 128 + c0 + cc) * 15;
        float s = bias[m];
        for (int d = 0; d < GS; d++) s = fmaf(W[m * GS + d], src[d], s);
        q[cc * GS + m] = s;
    }
    __syncthreads();

    // merge (grouped 1x1, 4 consecutive channels)
    for (int idx = t; idx < 32 * GS; idx += 256) {
        int f = idx / GS, pos = idx - f * GS;
        int i = 16 * g + (f >> 1), jm = f & 1;
        const float* qb = q + (4 * (f >> 1)) * GS + pos;
        float s = 0.0f;
        #pragma unroll
        for (int k = 0; k < 4; k++)
            s = fmaf(Wm[(i * 2 + jm) * 4 + k], qb[k * GS], s);
        Bs[f * GS + pos] = s;
    }
    __syncthreads();

    // Wih + bih
    for (int idx = t; idx < 96 * GS; idx += 256) {
        int o = idx / GS, pos = idx - o * GS;
        float s = bih[g * 96 + o];
        #pragma unroll 8
        for (int f = 0; f < 32; f++)
            s = fmaf(Wih[(g * 96 + o) * 32 + f], Bs[f * GS + pos], s);
        g_Gi[((b * 8 + g) * 96 + o) * 15 + pos] = s;
    }
}

// ============================================================================
// K4: fused main kernel (templated on pooled grid shape).
// grid = (128, 8): blockIdx.y = GRU group, blockIdx.x: b = x>>4, 8-row tile.
// Warp = one image row; thread = 4 consecutive pixels (2 f32x2 lanes).
// ============================================================================
template<int OH, int OW>
__device__ __forceinline__ void run_group(
    int g, const float* __restrict__ x, float* __restrict__ out,
    float* s_wpack, float* s_grow, float* s_bhh2)
{
    const int t = threadIdx.x;
    const int b = blockIdx.x >> 4;
    const int warp = t >> 5, lane = t & 31;
    const int h = ((blockIdx.x & 15) << 3) + warp;
    const int wbase = lane * 4;

    const float* gib = g_Gi + (size_t)((b * 8 + g) * 96) * 15;

    // build row-interpolated Gi grid
    if (OH == 1) {
        for (int idx = t; idx < 96 * OW; idx += 256) {
            int o = idx / OW, jj = idx - o * OW;
            s_grow[idx] = gib[o * 15 + jj];
        }
    } else {
        float src = (float)(h * (OH - 1)) * (1.0f / 127.0f);
        int ih0 = (int)src; if (ih0 > OH - 2) ih0 = OH - 2;
        float fh = src - (float)ih0;
        for (int idx = lane; idx < 96 * OW; idx += 32) {
            int o = idx / OW, jj = idx - o * OW;
            float v0 = gib[o * 15 + ih0 * OW + jj];
            float v1 = gib[o * 15 + (ih0 + 1) * OW + jj];
            s_grow[warp * 96 * OW + idx] = fmaf(fh, v1 - v0, v0);
        }
    }
    __syncthreads();

    const float* gr = (OH == 1) ? s_grow : (s_grow + warp * 96 * OW);

    // w-interp params
    int j0[4]; float fwv[4];
    if (OW > 1) {
        #pragma unroll
        for (int s = 0; s < 4; s++) {
            int w = wbase + s;
            float src = (float)(w * (OW - 1)) * (1.0f / 127.0f);
            int jj = (int)src; if (jj > OW - 2) jj = OW - 2;
            j0[s] = jj; fwv[s] = src - (float)jj;
        }
    }

    // load 16 input channels for 4 pixels, packed as f32x2
    uint64_t xp0[16], xp1[16];
    const float* xb = x + (((size_t)b * CINCH + g * 16) * HDIM + h) * WDIM + wbase;
    #pragma unroll
    for (int c = 0; c < 16; c++) {
        float4 v = *(const float4*)(xb + (size_t)c * (HDIM * WDIM));
        xp0[c] = pack2(v.x, v.y);
        xp1[c] = pack2(v.z, v.w);
    }

    float* outb = out + (((size_t)b * 256) * HDIM + h) * WDIM + wbase;

    #pragma unroll 1
    for (int j = 0; j < 32; j++) {
        uint64_t ar0 = *(const uint64_t*)&s_bhh2[2 * j];        uint64_t ar1 = ar0;
        uint64_t az0 = *(const uint64_t*)&s_bhh2[2 * (32 + j)]; uint64_t az1 = az0;
        uint64_t an0 = *(const uint64_t*)&s_bhh2[2 * (64 + j)]; uint64_t an1 = an0;
        uint64_t ac0 = 0, ac1 = 0;

        const ulonglong2* wp = (const ulonglong2*)(s_wpack + j * 128);
        #pragma unroll
        for (int i = 0; i < 16; i++) {
            ulonglong2 wa = wp[2 * i];       // {r,r},{z,z}
            ulonglong2 wb = wp[2 * i + 1];   // {n,n},{c,c}
            ffma2(ar0, wa.x, xp0[i]); ffma2(ar1, wa.x, xp1[i]);
            ffma2(az0, wa.y, xp0[i]); ffma2(az1, wa.y, xp1[i]);
            ffma2(an0, wb.x, xp0[i]); ffma2(an1, wb.x, xp1[i]);
            ffma2(ac0, wb.y, xp0[i]); ffma2(ac1, wb.y, xp1[i]);
        }

        float hr[4], hz[4], hn[4], cg[4];
        unpack2(ar0, hr[0], hr[1]); unpack2(ar1, hr[2], hr[3]);
        unpack2(az0, hz[0], hz[1]); unpack2(az1, hz[2], hz[3]);
        unpack2(an0, hn[0], hn[1]); unpack2(an1, hn[2], hn[3]);
        unpack2(ac0, cg[0], cg[1]); unpack2(ac1, cg[2], cg[3]);

        const float* Qr = gr + j * OW;
        const float* Qz = gr + (32 + j) * OW;
        const float* Qn = gr + (64 + j) * OW;

        float gir_u = 0.f, giz_u = 0.f, gin_u = 0.f;
        if (OW == 1) { gir_u = Qr[0]; giz_u = Qz[0]; gin_u = Qn[0]; }

        float res[4];
        #pragma unroll
        for (int s = 0; s < 4; s++) {
            float gir, giz, gin;
            if (OW == 1) { gir = gir_u; giz = giz_u; gin = gin_u; }
            else {
                float q0 = Qr[j0[s]], q1 = Qr[j0[s] + 1];
                gir = fmaf(fwv[s], q1 - q0, q0);
                q0 = Qz[j0[s]]; q1 = Qz[j0[s] + 1];
                giz = fmaf(fwv[s], q1 - q0, q0);
                q0 = Qn[j0[s]]; q1 = Qn[j0[s] + 1];
                gin = fmaf(fwv[s], q1 - q0, q0);
            }
            float rr = sigfast(gir + hr[s]);
            float zz = sigfast(giz + hz[s]);
            float nn = tanhfast(fmaf(rr, hn[s], gin));
            res[s] = fmaf(zz, cg[s] - nn, nn);   // (1-z)*n + z*cg
        }
        *(float4*)(outb + (size_t)(j * 8 + g) * (HDIM * WDIM)) =
            make_float4(res[0], res[1], res[2], res[3]);
    }
}

__global__ __launch_bounds__(256) void main_kernel(
    const float* __restrict__ x, const float* __restrict__ Wcen,
    const float* __restrict__ bhh, float* __restrict__ out)
{
    __shared__ float s_wpack[32 * 16 * 8];   // per (j,i): {r,r,z,z,n,n,c,c}
    __shared__ float s_grow[3840];           // row-interp Gi (max 8*96*5)
    __shared__ float s_bhh2[192];            // duplicated bias pairs

    const int g = blockIdx.y;
    const int t = threadIdx.x;

    // build duplicated weight pairs
    for (int idx = t; idx < 512; idx += 256) {
        int j = idx >> 4, i = idx & 15;
        float r = g_Wfold[(g * 96 + j) * 16 + i];
        float z = g_Wfold[(g * 96 + 32 + j) * 16 + i];
        float n = g_Wfold[(g * 96 + 64 + j) * 16 + i];
        float c = Wcen[(g * 32 + j) * 16 + i];
        float* dst = s_wpack + j * 128 + i * 8;
        dst[0] = r; dst[1] = r; dst[2] = z; dst[3] = z;
        dst[4] = n; dst[5] = n; dst[6] = c; dst[7] = c;
    }
    if (t < 96) {
        float v = bhh[g * 96 + t];
        s_bhh2[2 * t] = v; s_bhh2[2 * t + 1] = v;
    }

    switch (g >> 1) {
        case 0:  run_group<1, 11>(g, x, out, s_wpack, s_grow, s_bhh2); break;
        case 1:  run_group<11, 1>(g, x, out, s_wpack, s_grow, s_bhh2); break;
        case 2:  run_group<3, 5>(g, x, out, s_wpack, s_grow, s_bhh2); break;
        default: run_group<5, 3>(g, x, out, s_wpack, s_grow, s_bhh2); break;
    }
}

// ============================================================================
extern "C" void kernel_launch(void* const* d_in, const int* in_sizes, int n_in,
                              void* d_out, int out_size) {
    (void)in_sizes; (void)n_in; (void)out_size;
    const float* x    = (const float*)d_in[0];
    const float* Wcen = (const float*)d_in[1];
    const float* W0 = (const float*)d_in[2];  const float* b0 = (const float*)d_in[3];
    const float* W1 = (const float*)d_in[4];  const float* b1 = (const float*)d_in[5];
    const float* W2 = (const float*)d_in[6];  const float* b2 = (const float*)d_in[7];
    const float* W3 = (const float*)d_in[8];  const float* b3 = (const float*)d_in[9];
    const float* Wm  = (const float*)d_in[10];
    const float* Wih = (const float*)d_in[11];
    const float* Whh = (const float*)d_in[12];
    const float* bih = (const float*)d_in[13];
    const float* bhh = (const float*)d_in[14];
    float* out = (float*)d_out;

    pool_kernel<<<1024, 128>>>(x);
    fold_kernel<<<8, 96>>>(Whh, Wcen);
    gi_kernel<<<64, 256>>>(W0, b0, W1, b1, W2, b2, W3, b3, Wm, Wih, bih);
    main_kernel<<<dim3(128, 8), 256>>>(x, Wcen, bhh, out);
}

// round 4
// speedup vs baseline: 3.0898x; 1.3432x over previous
#include <cuda_runtime.h>
#include <stdint.h>

#define HW 16384   // 128*128

// ---- device scratch ----
__device__ float g_pool[4 * 8 * 128 * 15];   // [br][b][c][pos]
__device__ float g_Wfold[8 * 96 * 16];       // Whh @ W_center per group
__device__ float g_Gi[8 * 8 * 96 * 15];      // [b][g][o][pos] (includes bih)

// ---- helpers ----
__device__ __forceinline__ float tanhfast(float x) {
    float y; asm("tanh.approx.f32 %0, %1;" : "=f"(y) : "f"(x)); return y;
}
__device__ __forceinline__ float sigfast(float x) {
    return fmaf(0.5f, tanhfast(0.5f * x), 0.5f);
}
__device__ __forceinline__ uint32_t cvt_tf32(float f) {
    uint32_t r; asm("cvt.rna.tf32.f32 %0, %1;" : "=r"(r) : "f"(f)); return r;
}
__device__ __forceinline__ void mma_acc(float d[4], const uint32_t a[4],
                                        uint32_t b0, uint32_t b1) {
    asm("mma.sync.aligned.m16n8k8.row.col.f32.tf32.tf32.f32 "
        "{%0,%1,%2,%3},{%4,%5,%6,%7},{%8,%9},{%0,%1,%2,%3};"
        : "+f"(d[0]), "+f"(d[1]), "+f"(d[2]), "+f"(d[3])
        : "r"(a[0]), "r"(a[1]), "r"(a[2]), "r"(a[3]), "r"(b0), "r"(b1));
}
__device__ __forceinline__ void mma_init(float d[4], const uint32_t a[4],
                                         uint32_t b0, uint32_t b1,
                                         float c0, float c1) {
    asm("mma.sync.aligned.m16n8k8.row.col.f32.tf32.tf32.f32 "
        "{%0,%1,%2,%3},{%4,%5,%6,%7},{%8,%9},{%10,%11,%10,%11};"
        : "=f"(d[0]), "=f"(d[1]), "=f"(d[2]), "=f"(d[3])
        : "r"(a[0]), "r"(a[1]), "r"(a[2]), "r"(a[3]), "r"(b0), "r"(b1),
          "f"(c0), "f"(c1));
}

// ============================================================================
// K1: single-pass adaptive pools. Block per (b,c), 128 threads = columns.
// ============================================================================
__global__ __launch_bounds__(128) void pool_kernel(const float* __restrict__ x) {
    const int bc = blockIdx.x;
    const int b = bc >> 7, c = bc & 127;
    const float* tile = x + (size_t)bc * HW;
    const int t = threadIdx.x;

    float a0 = 0.0f;
    float a1[11], a2[3], a3[5];
    #pragma unroll
    for (int i = 0; i < 11; i++) a1[i] = 0.0f;
    #pragma unroll
    for (int i = 0; i < 3; i++) a2[i] = 0.0f;
    #pragma unroll
    for (int i = 0; i < 5; i++) a3[i] = 0.0f;

    #pragma unroll
    for (int h = 0; h < 128; h++) {
        float v = tile[h * 128 + t];
        a0 += v;
        {
            const int p = (h * 11) >> 7;
            a1[p] += v;
            if (p + 1 < 11 && h == ((p + 1) * 128) / 11 && (((p + 1) * 128) % 11) != 0)
                a1[p + 1] += v;
        }
        {
            const int p = (h * 3) >> 7;
            a2[p] += v;
            if (p + 1 < 3 && h == ((p + 1) * 128) / 3 && (((p + 1) * 128) % 3) != 0)
                a2[p + 1] += v;
        }
        {
            const int p = (h * 5) >> 7;
            a3[p] += v;
            if (p + 1 < 5 && h == ((p + 1) * 128) / 5 && (((p + 1) * 128) % 5) != 0)
                a3[p + 1] += v;
        }
    }

    __shared__ float cs[20][128];
    cs[0][t] = a0;
    #pragma unroll
    for (int i = 0; i < 11; i++) cs[1 + i][t] = a1[i];
    #pragma unroll
    for (int i = 0; i < 3; i++) cs[12 + i][t] = a2[i];
    #pragma unroll
    for (int i = 0; i < 5; i++) cs[15 + i][t] = a3[i];
    __syncthreads();

    const int warp = t >> 5, lane = t & 31;
    for (int oi = warp; oi < 52; oi += 4) {
        int br, pos, row, ws, we, hs, he;
        if (oi < 11) {
            br = 0; pos = oi; row = 0;
            hs = 0; he = 128;
            ws = (pos * 128) / 11; we = ((pos + 1) * 128 + 10) / 11;
        } else if (oi < 22) {
            br = 1; pos = oi - 11; row = 1 + pos;
            ws = 0; we = 128;
            hs = (pos * 128) / 11; he = ((pos + 1) * 128 + 10) / 11;
        } else if (oi < 37) {
            br = 2; pos = oi - 22;
            int i = pos / 5, jj = pos % 5;
            row = 12 + i;
            hs = (i * 128) / 3;  he = ((i + 1) * 128 + 2) / 3;
            ws = (jj * 128) / 5; we = ((jj + 1) * 128 + 4) / 5;
        } else {
            br = 3; pos = oi - 37;
            int i = pos / 3, jj = pos % 3;
            row = 15 + i;
            hs = (i * 128) / 5;  he = ((i + 1) * 128 + 4) / 5;
            ws = (jj * 128) / 3; we = ((jj + 1) * 128 + 2) / 3;
        }
        float s = 0.0f;
        for (int w = ws + lane; w < we; w += 32) s += cs[row][w];
        #pragma unroll
        for (int off = 16; off; off >>= 1) s += __shfl_down_sync(0xffffffffu, s, off);
        if (lane == 0)
            g_pool[((br * 8 + b) * 128 + c) * 15 + pos] =
                s / (float)((he - hs) * (we - ws));
    }
}

// ============================================================================
// K2: fused branch-linear + merge + Wih -> Gi grid (blocks 0..63),
//     plus Wfold = Whh @ W_center (blocks 64..71).
// ============================================================================
__global__ __launch_bounds__(256) void gi_fold_kernel(
    const float* __restrict__ W0, const float* __restrict__ b0,
    const float* __restrict__ W1, const float* __restrict__ b1,
    const float* __restrict__ W2, const float* __restrict__ b2,
    const float* __restrict__ W3, const float* __restrict__ b3,
    const float* __restrict__ Wm, const float* __restrict__ Wih,
    const float* __restrict__ bih,
    const float* __restrict__ Whh, const float* __restrict__ Wcen)
{
    const int blk = blockIdx.x;
    const int t = threadIdx.x;

    if (blk >= 64) {               // fold part
        int g = blk - 64;
        if (t < 96) {
            int o = t;
            #pragma unroll 4
            for (int i = 0; i < 16; i++) {
                float s = 0.0f;
                #pragma unroll
                for (int hh = 0; hh < 32; hh++)
                    s = fmaf(Whh[(g * 96 + o) * 32 + hh], Wcen[(g * 32 + hh) * 16 + i], s);
                g_Wfold[(g * 96 + o) * 16 + i] = s;
            }
        }
        return;
    }

    const int b = blk >> 3, g = blk & 7;
    const int br = g >> 1;
    const int GS = (br < 2) ? 11 : 15;
    const float* Ws[4] = {W0, W1, W2, W3};
    const float* bs[4] = {b0, b1, b2, b3};
    const float* W = Ws[br];
    const float* bias = bs[br];
    const int c0 = 64 * (g & 1);

    __shared__ float q[64 * 15];
    __shared__ float Bs[32 * 15];

    for (int idx = t; idx < 64 * GS; idx += 256) {
        int cc = idx / GS, m = idx - cc * GS;
        const float* src = g_pool + ((br * 8 + b) * 128 + c0 + cc) * 15;
        float s = bias[m];
        for (int d = 0; d < GS; d++) s = fmaf(W[m * GS + d], src[d], s);
        q[cc * GS + m] = s;
    }
    __syncthreads();

    for (int idx = t; idx < 32 * GS; idx += 256) {
        int f = idx / GS, pos = idx - f * GS;
        int i = 16 * g + (f >> 1), jm = f & 1;
        const float* qb = q + (4 * (f >> 1)) * GS + pos;
        float s = 0.0f;
        #pragma unroll
        for (int k = 0; k < 4; k++)
            s = fmaf(Wm[(i * 2 + jm) * 4 + k], qb[k * GS], s);
        Bs[f * GS + pos] = s;
    }
    __syncthreads();

    for (int idx = t; idx < 96 * GS; idx += 256) {
        int o = idx / GS, pos = idx - o * GS;
        float s = bih[g * 96 + o];
        #pragma unroll 8
        for (int f = 0; f < 32; f++)
            s = fmaf(Wih[(g * 96 + o) * 32 + f], Bs[f * GS + pos], s);
        g_Gi[((b * 8 + g) * 96 + o) * 15 + pos] = s;
    }
}

// ============================================================================
// K3: main fused kernel via mma.sync tf32.
// grid (128, 8): blockIdx.y = group g; b = blockIdx.x>>4; warp = one image row.
// Per warp: 8 M-tiles of 16 pixels. N = 128 outputs = 16 N-tiles:
//   tiles 0-3: r_j, 4-7: z_j, 8-11: hn_j (C-init = bhh_n), 12-15: cg_j.
// Thread epilogue: pixels {p, p+8}, j in {8T+2q, 8T+2q+1}.
// ============================================================================
template<int OH, int OW>
__device__ __forceinline__ void run_group(
    int g, int b, const float* __restrict__ x, const float* __restrict__ bhh,
    float* __restrict__ out, const float2* Wsm, float* xsp, float* grow)
{
    const int t = threadIdx.x;
    const int warp = t >> 5, lane = t & 31;
    const int p = lane >> 2, q = lane & 3;
    const int h = ((blockIdx.x & 15) << 3) + warp;

    // ---- per-warp (or shared) row-interpolated Gi grid, bhh_r/z folded in ----
    const float* gib = g_Gi + (size_t)((b * 8 + g) * 96) * 15;
    if (OH == 1) {
        for (int idx = t; idx < 96 * OW; idx += 256) {
            int j = idx / OW, pos = idx - j * OW;
            float v = gib[j * 15 + pos];
            if (j < 64) v += bhh[g * 96 + j];
            grow[idx] = v;
        }
    } else {
        float src = (float)(h * (OH - 1)) * (1.0f / 127.0f);
        int ih0 = (int)src; if (ih0 > OH - 2) ih0 = OH - 2;
        float fh = src - (float)ih0;
        for (int idx = lane; idx < 96 * OW; idx += 32) {
            int j = idx / OW, pos = idx - j * OW;
            float v0 = gib[j * 15 + ih0 * OW + pos];
            float v1 = gib[j * 15 + (ih0 + 1) * OW + pos];
            float v = fmaf(fh, v1 - v0, v0);
            if (j < 64) v += bhh[g * 96 + j];
            grow[warp * 96 * OW + idx] = v;
        }
    }
    __syncthreads();

    const float* gw = (OH == 1) ? grow : (grow + warp * 96 * OW);
    float* xw = xsp + warp * 288;      // 16 px * 18 floats

    // bhh_n pairs for hn-tile C-init
    float bn[8];
    #pragma unroll
    for (int T = 0; T < 4; T++) {
        bn[2 * T]     = bhh[g * 96 + 64 + 8 * T + 2 * q];
        bn[2 * T + 1] = bhh[g * 96 + 64 + 8 * T + 2 * q + 1];
    }

    const float* xrow = x + ((size_t)(b * 128 + g * 16)) * HW + h * 128;
    float* outrow = out + ((size_t)b * 256 + g) * HW + h * 128;

    const int cch = lane >> 1, ph = lane & 1;
    const int slot = ((cch >> 3) * 4 + (cch & 3)) * 2 + ((cch >> 2) & 1);

    for (int tile = 0; tile < 8; tile++) {
        // ---- stage x tile (16px x 16ch), tf32-converted, pair-permuted ----
        const float* src = xrow + (size_t)cch * HW + tile * 16 + 8 * ph;
        float4 va = *(const float4*)src;
        float4 vb = *(const float4*)(src + 4);
        float* dst = xw + (8 * ph) * 18 + slot;
        dst[0 * 18] = __uint_as_float(cvt_tf32(va.x));
        dst[1 * 18] = __uint_as_float(cvt_tf32(va.y));
        dst[2 * 18] = __uint_as_float(cvt_tf32(va.z));
        dst[3 * 18] = __uint_as_float(cvt_tf32(va.w));
        dst[4 * 18] = __uint_as_float(cvt_tf32(vb.x));
        dst[5 * 18] = __uint_as_float(cvt_tf32(vb.y));
        dst[6 * 18] = __uint_as_float(cvt_tf32(vb.z));
        dst[7 * 18] = __uint_as_float(cvt_tf32(vb.w));
        __syncwarp();

        // ---- A fragments (pixels x K16) ----
        uint32_t A[2][4];
        #pragma unroll
        for (int s = 0; s < 2; s++) {
            float2 lo = *(const float2*)(xw + p * 18 + (s * 4 + q) * 2);
            float2 hi = *(const float2*)(xw + (p + 8) * 18 + (s * 4 + q) * 2);
            A[s][0] = __float_as_uint(lo.x);
            A[s][1] = __float_as_uint(hi.x);
            A[s][2] = __float_as_uint(lo.y);
            A[s][3] = __float_as_uint(hi.y);
        }

        // ---- 16 N-tiles x 2 k-steps ----
        float acc[16][4];
        #pragma unroll
        for (int T = 0; T < 16; T++) {
            float2 B0 = Wsm[(0 + q) * 132 + 8 * T + p];
            float2 B1 = Wsm[(4 + q) * 132 + 8 * T + p];
            float c0 = 0.0f, c1 = 0.0f;
            if (T >= 8 && T < 12) { c0 = bn[2 * (T - 8)]; c1 = bn[2 * (T - 8) + 1]; }
            mma_init(acc[T], A[0], __float_as_uint(B0.x), __float_as_uint(B0.y), c0, c1);
            mma_acc(acc[T], A[1], __float_as_uint(B1.x), __float_as_uint(B1.y));
        }
        __syncwarp();   // protect xw WAR for next tile's staging

        // ---- epilogue: GRU combine + bilinear gi + store ----
        int pxl[2] = {tile * 16 + p, tile * 16 + p + 8};
        int j0w[2]; float fw[2];
        if (OW > 1) {
            #pragma unroll
            for (int e = 0; e < 2; e++) {
                float s = (float)(pxl[e] * (OW - 1)) * (1.0f / 127.0f);
                int jj = (int)s; if (jj > OW - 2) jj = OW - 2;
                j0w[e] = jj; fw[e] = s - (float)jj;
            }
        }
        #pragma unroll
        for (int T = 0; T < 4; T++) {
            #pragma unroll
            for (int i = 0; i < 4; i++) {
                const int e = i >> 1;
                const int j = 8 * T + 2 * q + (i & 1);
                float ar = acc[T][i], az = acc[T + 4][i];
                float hn = acc[T + 8][i], cg = acc[T + 12][i];
                float gr, gz, gn;
                if (OW == 1) {
                    gr = gw[j]; gz = gw[32 + j]; gn = gw[64 + j];
                } else {
                    const float* Q = gw + j * OW + j0w[e];
                    gr = fmaf(fw[e], Q[1] - Q[0], Q[0]);
                    Q = gw + (32 + j) * OW + j0w[e];
                    gz = fmaf(fw[e], Q[1] - Q[0], Q[0]);
                    Q = gw + (64 + j) * OW + j0w[e];
                    gn = fmaf(fw[e], Q[1] - Q[0], Q[0]);
                }
                float r = sigfast(gr + ar);
                float z = sigfast(gz + az);
                float n = tanhfast(fmaf(r, hn, gn));
                outrow[(size_t)(j * 8) * HW + pxl[e]] = fmaf(z, cg - n, n);
            }
        }
    }
}

__global__ __launch_bounds__(256) void main_kernel(
    const float* __restrict__ x, const float* __restrict__ Wcen,
    const float* __restrict__ bhh, float* __restrict__ out)
{
    __shared__ __align__(16) float2 Wsm[8 * 132];      // weight pairs, tf32 bits
    __shared__ __align__(16) float xsp[8 * 288];       // per-warp staged x
    __shared__ __align__(16) float grow[3840];         // row-interp Gi grids

    const int g = blockIdx.y;
    const int b = blockIdx.x >> 4;
    const int t = threadIdx.x;

    // build weight-pair matrix: W[k][col], col<96 -> Wfold, col>=96 -> Wcen
    for (int idx = t; idx < 1024; idx += 256) {
        int qh = idx >> 7, col = idx & 127;
        int s = qh >> 2, q = qh & 3;
        int k0 = 8 * s + q, k1 = k0 + 4;
        float w0, w1;
        if (col < 96) {
            w0 = g_Wfold[(g * 96 + col) * 16 + k0];
            w1 = g_Wfold[(g * 96 + col) * 16 + k1];
        } else {
            w0 = Wcen[(g * 32 + col - 96) * 16 + k0];
            w1 = Wcen[(g * 32 + col - 96) * 16 + k1];
        }
        Wsm[qh * 132 + col] = make_float2(__uint_as_float(cvt_tf32(w0)),
                                          __uint_as_float(cvt_tf32(w1)));
    }
    // (grow build + __syncthreads happen inside run_group)

    switch (g >> 1) {
        case 0:  run_group<1, 11>(g, b, x, bhh, out, Wsm, xsp, grow); break;
        case 1:  run_group<11, 1>(g, b, x, bhh, out, Wsm, xsp, grow); break;
        case 2:  run_group<3, 5>(g, b, x, bhh, out, Wsm, xsp, grow); break;
        default: run_group<5, 3>(g, b, x, bhh, out, Wsm, xsp, grow); break;
    }
}

// ============================================================================
extern "C" void kernel_launch(void* const* d_in, const int* in_sizes, int n_in,
                              void* d_out, int out_size) {
    (void)in_sizes; (void)n_in; (void)out_size;
    const float* x    = (const float*)d_in[0];
    const float* Wcen = (const float*)d_in[1];
    const float* W0 = (const float*)d_in[2];  const float* b0 = (const float*)d_in[3];
    const float* W1 = (const float*)d_in[4];  const float* b1 = (const float*)d_in[5];
    const float* W2 = (const float*)d_in[6];  const float* b2 = (const float*)d_in[7];
    const float* W3 = (const float*)d_in[8];  const float* b3 = (const float*)d_in[9];
    const float* Wm  = (const float*)d_in[10];
    const float* Wih = (const float*)d_in[11];
    const float* Whh = (const float*)d_in[12];
    const float* bih = (const float*)d_in[13];
    const float* bhh = (const float*)d_in[14];
    float* out = (float*)d_out;

    pool_kernel<<<1024, 128>>>(x);
    gi_fold_kernel<<<72, 256>>>(W0, b0, W1, b1, W2, b2, W3, b3,
                                Wm, Wih, bih, Whh, Wcen);
    main_kernel<<<dim3(128, 8), 256>>>(x, Wcen, bhh, out);
}